// round 4
// baseline (speedup 1.0000x reference)
#include <cuda_runtime.h>
#include <cuda_fp16.h>
#include <cstdint>

// ---------------- scratch (static device globals) ---------------------------
__device__ __half g_votes[256u * 1152u * 160u];  // fp16 votes, ~94 MB
__device__ float  g_s[3][256 * 160];             // per-pass s partials (atomics)

// ---------------- constants -------------------------------------------------
#define NB      256
#define NN      1152
#define NC      10
#define CO      160
#define ROW     160           // halves per (b,n) row
#define GN      16            // n's per votes block
#define NGRP    (NN/GN)       // 72
#define TILE_N  32
#define SPLIT   6             // n-chunks per batch (routing)
#define CHUNK_T 6             // tiles per chunk (192 n)
#define CHUNK_N (TILE_N*CHUNK_T)
#define TILE_H  (TILE_N*ROW)  // 5120 halves = 10240 B per tile
#define POSE_OFF   0
#define ACT_OFF    40960
#define COUP_OFF   43520

// ---------------- cp.async helpers -----------------------------------------
__device__ __forceinline__ void cp_async16(void* smem_dst, const void* gsrc) {
    unsigned s = (unsigned)__cvta_generic_to_shared(smem_dst);
    asm volatile("cp.async.cg.shared.global [%0], [%1], 16;\n" :: "r"(s), "l"(gsrc));
}
__device__ __forceinline__ void cp_commit() {
    asm volatile("cp.async.commit_group;\n");
}
template <int N>
__device__ __forceinline__ void cp_wait() {
    asm volatile("cp.async.wait_group %0;\n" :: "n"(N));
}

// squash over a 16-lane o-group (caller guarantees full-warp participation)
__device__ __forceinline__ float squash16(float s) {
    float sq = s * s;
#pragma unroll
    for (int m = 1; m < 16; m <<= 1)
        sq += __shfl_xor_sync(0xFFFFFFFFu, sq, m, 16);
    float norm = sqrtf(sq + 1e-8f);
    return sq / (1.0f + sq) * (s / norm);
}

// ============================================================================
// init: zero the atomic accumulators (re-zeroed every graph replay)
// ============================================================================
__global__ void init_kernel() {
    int i = blockIdx.x * blockDim.x + threadIdx.x;
    if (i < 3 * NB * CO) ((float*)g_s)[i] = 0.f;
}

// ============================================================================
// Kernel A: votes[b,n,c,o] = sum_i W[n,c,o,i]*P[b,n,i]  (fp32 math, fp16 out)
// PLUS fused pass-0 accumulation: g_s[0][b,co] += 0.1 * sum_n votes.
// grid (72 n-groups, 8 bc): block covers 16 n x 32 b. 160 threads:
//   co4 = t%40 owns 4 consecutive co outputs, bsub = t/40 strides b by 4.
// ============================================================================
__global__ __launch_bounds__(160) void votes_kernel(
    const float* __restrict__ P, const float* __restrict__ W)
{
    const int ng   = blockIdx.x;
    const int bc   = blockIdx.y;
    const int t    = threadIdx.x;
    const int co4  = t % 40;
    const int bsub = t / 40;

    __shared__ float sp[32 * 16];

    float acc[32];                         // s0 partial: 8 b-slots x 4 co
#pragma unroll
    for (int q = 0; q < 32; q++) acc[q] = 0.f;

    for (int g = 0; g < GN; g++) {
        const int n = ng * GN + g;

        __syncthreads();                   // prior reads of sp done
        for (int idx = t; idx < 512; idx += 160) {
            int bl = idx >> 4, i = idx & 15;
            sp[idx] = P[(size_t)(bc * 32 + bl) * (NN * 16) + (size_t)n * 16 + i];
        }

        float w[64];
        const float4* Wv = (const float4*)(W + ((size_t)n * CO + co4 * 4) * 16);
#pragma unroll
        for (int q = 0; q < 16; q++) {
            float4 x = Wv[q];
            w[q*4+0] = x.x; w[q*4+1] = x.y; w[q*4+2] = x.z; w[q*4+3] = x.w;
        }
        __syncthreads();

#pragma unroll
        for (int q = 0; q < 8; q++) {
            const int bl = bsub + 4 * q;
            float p[16];
            const float4* pv = (const float4*)(sp + bl * 16);
#pragma unroll
            for (int j = 0; j < 4; j++) {
                float4 x = pv[j];
                p[j*4+0] = x.x; p[j*4+1] = x.y; p[j*4+2] = x.z; p[j*4+3] = x.w;
            }
            float a0 = 0.f, a1 = 0.f, a2 = 0.f, a3 = 0.f;
#pragma unroll
            for (int i = 0; i < 16; i++) {
                a0 = fmaf(w[i],      p[i], a0);
                a1 = fmaf(w[16 + i], p[i], a1);
                a2 = fmaf(w[32 + i], p[i], a2);
                a3 = fmaf(w[48 + i], p[i], a3);
            }
            acc[q*4+0] += a0; acc[q*4+1] += a1;
            acc[q*4+2] += a2; acc[q*4+3] += a3;

            union { __half2 h[2]; uint2 u; } pk;
            pk.h[0] = __floats2half2_rn(a0, a1);
            pk.h[1] = __floats2half2_rn(a2, a3);
            *(uint2*)(g_votes + ((size_t)(bc * 32 + bl) * NN + n) * ROW + co4 * 4) = pk.u;
        }
    }

    // fused pass-0: s0 += 0.1 * partial sums (32 atomics per thread)
#pragma unroll
    for (int q = 0; q < 8; q++) {
        const int b = bc * 32 + bsub + 4 * q;
#pragma unroll
        for (int j = 0; j < 4; j++)
            atomicAdd(&g_s[0][b * CO + co4 * 4 + j], 0.1f * acc[q*4+j]);
    }
}

// ============================================================================
// Kernel B: routing pass over 192 n's. grid (256 b, 6 chunks), 512 threads =
// 32 n-slots x 16 c-lanes (c<10 active). Each block recomputes the needed
// v-sum from g_s (pass1: v0; pass2: v0+v1), then streams votes, softmax,
// accumulates s partials -> atomicAdd. PASS 2 also writes coupling.
// ============================================================================
template <int PASS>
__global__ __launch_bounds__(512, 2) void route_kernel(
    const float* __restrict__ bias, float* __restrict__ out)
{
    const int b     = blockIdx.x;
    const int chunk = blockIdx.y;
    const int t     = threadIdx.x;
    const int nl    = t >> 4;
    const int cl    = t & 15;

    // smem: 2 fp16 tiles (20480B) + svsum(640B) + ccs(2048B)
    __shared__ __align__(16) unsigned char smbuf[2 * TILE_H * 2 + 160 * 4 + 512 * 4];
    __half* tile0 = (__half*)smbuf;
    __half* tile1 = tile0 + TILE_H;
    float*  svsum = (float*)(smbuf + 2 * TILE_H * 2);
    float*  ccs   = svsum + 160;

    const __half* vb = g_votes + (size_t)b * (NN * ROW) + (size_t)chunk * (CHUNK_N * ROW);

    // prefetch tile 0 (640 x 16B)
#pragma unroll
    for (int i = 0; i < 2; i++) {
        int idx = t + i * 512;
        if (idx < TILE_H / 8) cp_async16(tile0 + idx * 8, vb + idx * 8);
    }
    cp_commit();

    // ---- recompute v-sum from global s partials (t<160: 5 full warps) ----
    if (t < 160) {
        float bs = bias[t];
        float v = squash16(g_s[0][b * CO + t] + bs);
        if (PASS == 2)
            v += squash16(g_s[1][b * CO + t] + bs);
        svsum[t] = v;
    }

    float sacc[16];
#pragma unroll
    for (int o = 0; o < 16; o++) sacc[o] = 0.f;

    __syncthreads();   // svsum visible

    for (int k = 0; k < CHUNK_T; k++) {
        __half* cur = (k & 1) ? tile1 : tile0;
        __half* nxt = (k & 1) ? tile0 : tile1;
        if (k + 1 < CHUNK_T) {
            const __half* src = vb + (size_t)(k + 1) * TILE_H;
#pragma unroll
            for (int i = 0; i < 2; i++) {
                int idx = t + i * 512;
                if (idx < TILE_H / 8) cp_async16(nxt + idx * 8, src + idx * 8);
            }
            cp_commit();
            cp_wait<1>();
        } else {
            cp_wait<0>();
        }
        __syncthreads();

        // ---- this (n,c)'s 16-vector ----
        float vv[16];
        if (cl < 10) {
            const uint4* rp = (const uint4*)(cur + nl * ROW + cl * 16);
#pragma unroll
            for (int j = 0; j < 2; j++) {
                uint4 q = rp[j];
                float2 f0 = __half22float2(*(__half2*)&q.x);
                float2 f1 = __half22float2(*(__half2*)&q.y);
                float2 f2 = __half22float2(*(__half2*)&q.z);
                float2 f3 = __half22float2(*(__half2*)&q.w);
                vv[j*8+0]=f0.x; vv[j*8+1]=f0.y; vv[j*8+2]=f1.x; vv[j*8+3]=f1.y;
                vv[j*8+4]=f2.x; vv[j*8+5]=f2.y; vv[j*8+6]=f3.x; vv[j*8+7]=f3.y;
            }
        } else {
#pragma unroll
            for (int o = 0; o < 16; o++) vv[o] = 0.f;
        }

        // ---- logit + softmax over c (width-16 shuffles) ----
        float lg;
        if (cl < 10) {
            lg = 0.f;
            const float4* sv = (const float4*)(svsum + cl * 16);
#pragma unroll
            for (int j = 0; j < 4; j++) {
                float4 x = sv[j];
                lg = fmaf(x.x, vv[j*4+0], lg);
                lg = fmaf(x.y, vv[j*4+1], lg);
                lg = fmaf(x.z, vv[j*4+2], lg);
                lg = fmaf(x.w, vv[j*4+3], lg);
            }
        } else {
            lg = -1e30f;
        }
        float mx = lg;
#pragma unroll
        for (int m = 1; m < 16; m <<= 1)
            mx = fmaxf(mx, __shfl_xor_sync(0xFFFFFFFFu, mx, m, 16));
        float e = (cl < 10) ? __expf(lg - mx) : 0.f;
        float den = e;
#pragma unroll
        for (int m = 1; m < 16; m <<= 1)
            den += __shfl_xor_sync(0xFFFFFFFFu, den, m, 16);
        float cc = e / den;

#pragma unroll
        for (int o = 0; o < 16; o++) sacc[o] = fmaf(cc, vv[o], sacc[o]);

        if (PASS == 2) {
            if (cl < 10) ccs[nl * 16 + cl] = cc;
            __syncthreads();
            if (t < 320) {
                int c2 = t / 32, nn = t % 32;
                out[COUP_OFF + (size_t)b * (NC * NN) + (size_t)c2 * NN
                    + chunk * CHUNK_N + k * TILE_N + nn] = ccs[nn * 16 + c2];
            }
        }
        __syncthreads();
    }

    // ---- cross-slot reduction of s partials ----
#pragma unroll
    for (int o = 0; o < 16; o++)
        sacc[o] += __shfl_xor_sync(0xFFFFFFFFu, sacc[o], 16, 32);

    float* sred = (float*)smbuf;      // tiles are done; 16 warps x 256 floats
    const int wid = t >> 5;
    if ((t & 16) == 0) {
#pragma unroll
        for (int j = 0; j < 4; j++) {
            float4 x = make_float4(sacc[j*4], sacc[j*4+1], sacc[j*4+2], sacc[j*4+3]);
            *(float4*)(sred + wid * 256 + cl * 16 + j * 4) = x;
        }
    }
    __syncthreads();

    if (t < 160) {
        float s = 0.f;
#pragma unroll
        for (int w2 = 0; w2 < 16; w2++) s += sred[w2 * 256 + t];
        atomicAdd(&g_s[PASS][b * CO + t], s);
    }
}

// ============================================================================
// finish2: final outputs from complete s2. grid 256, 160 threads.
// ============================================================================
__global__ __launch_bounds__(160) void finish2_kernel(
    const float* __restrict__ bias, float* __restrict__ out)
{
    const int b = blockIdx.x;
    const int t = threadIdx.x;
    const int c = t >> 4, o = t & 15;

    float v = squash16(g_s[2][b * CO + t] + bias[t]);

    out[POSE_OFF + (size_t)b * CO + t] = v;
    float vsq = v * v;
#pragma unroll
    for (int m = 1; m < 16; m <<= 1)
        vsq += __shfl_xor_sync(0xFFFFFFFFu, vsq, m, 16);
    if (o == 0) out[ACT_OFF + b * NC + c] = sqrtf(vsq + 1e-8f);
}

// ============================================================================
extern "C" void kernel_launch(void* const* d_in, const int* in_sizes, int n_in,
                              void* d_out, int out_size)
{
    const float* P    = (const float*)d_in[0];  // (256,32,6,6,16,1)
    const float* W    = (const float*)d_in[2];  // (32,6,6,10,16,16)
    const float* bias = (const float*)d_in[3];  // (10,1,1,16,1)
    float* out = (float*)d_out;

    init_kernel<<<(3 * NB * CO + 511) / 512, 512>>>();
    votes_kernel<<<dim3(NGRP, 8), 160>>>(P, W);
    route_kernel<1><<<dim3(NB, SPLIT), 512>>>(bias, out);
    route_kernel<2><<<dim3(NB, SPLIT), 512>>>(bias, out);
    finish2_kernel<<<NB, 160>>>(bias, out);
}

// round 5
// speedup vs baseline: 1.0423x; 1.0423x over previous
#include <cuda_runtime.h>
#include <cuda_fp16.h>
#include <cstdint>

// ---------------- scratch (static device globals) ---------------------------
__device__ __half g_votes[256u * 1152u * 160u];  // fp16 votes, ~94 MB
__device__ float  g_s[3][256 * 160];             // per-pass s accumulators

// ---------------- constants -------------------------------------------------
#define NB      256
#define NN      1152
#define NC      10
#define CO      160
#define ROW     160            // halves per (b,n) row
#define GN      8              // n's per votes block
#define NGRP    (NN/GN)        // 144
#define RSPLIT  12             // route chunks per batch
#define RCH     (NN/RSPLIT)    // 96 n per chunk
#define POSE_OFF   0
#define ACT_OFF    40960
#define COUP_OFF   43520

// ---------------- f32x2 helpers ---------------------------------------------
typedef unsigned long long u64t;
__device__ __forceinline__ u64t pack2(float lo, float hi) {
    u64t r; asm("mov.b64 %0, {%1, %2};" : "=l"(r) : "f"(lo), "f"(hi)); return r;
}
__device__ __forceinline__ void unpack2(u64t v, float& lo, float& hi) {
    asm("mov.b64 {%0, %1}, %2;" : "=f"(lo), "=f"(hi) : "l"(v));
}
__device__ __forceinline__ u64t fma2(u64t a, u64t b, u64t c) {
    u64t r; asm("fma.rn.f32x2 %0, %1, %2, %3;" : "=l"(r) : "l"(a), "l"(b), "l"(c)); return r;
}
__device__ __forceinline__ u64t add2(u64t a, u64t b) {
    u64t r; asm("add.rn.f32x2 %0, %1, %2;" : "=l"(r) : "l"(a), "l"(b)); return r;
}

// squash over a 16-lane o-group (full-warp participation required)
__device__ __forceinline__ float squash16(float s) {
    float sq = s * s;
#pragma unroll
    for (int m = 1; m < 16; m <<= 1)
        sq += __shfl_xor_sync(0xFFFFFFFFu, sq, m, 16);
    float norm = sqrtf(sq + 1e-8f);
    return sq / (1.0f + sq) * (s / norm);
}

// ============================================================================
// init: zero the s accumulators (re-zeroed every graph replay)
// ============================================================================
__global__ void init_kernel() {
    int i = blockIdx.x * blockDim.x + threadIdx.x;
    if (i < 3 * NB * CO) ((float*)g_s)[i] = 0.f;
}

// ============================================================================
// Kernel A: votes[b,n,c,o] = sum_i W[n,c,o,i]*P[b,n,i]  (f32x2 math, fp16 out)
// fused pass-0: g_s[0][b,co] += 0.1 * sum_n votes.
// grid (144, 8): block = 8 n x 32 b. 160 threads: co4=t%40 owns 4 outputs
// (2 f32x2 pairs), bsub=t/40 strides b by 4.
// ============================================================================
__global__ __launch_bounds__(160) void votes_kernel(
    const float* __restrict__ P, const float* __restrict__ W)
{
    const int ng   = blockIdx.x;
    const int bc   = blockIdx.y;
    const int t    = threadIdx.x;
    const int co4  = t % 40;
    const int bsub = t / 40;

    __shared__ float sp[32 * 16];

    u64t s0acc[16];                  // 8 b-slots x 2 output-pairs
#pragma unroll
    for (int q = 0; q < 16; q++) s0acc[q] = 0ull;

    for (int g = 0; g < GN; g++) {
        const int n = ng * GN + g;

        __syncthreads();             // prior reads of sp done
        for (int idx = t; idx < 512; idx += 160) {
            int bl = idx >> 4, i = idx & 15;
            sp[idx] = P[(size_t)(bc * 32 + bl) * (NN * 16) + (size_t)n * 16 + i];
        }

        // load 4 W rows, pack into output-pair f32x2: w2[i]=(o0,o1), w2[16+i]=(o2,o3)
        u64t w2[32];
        const float4* Wv = (const float4*)(W + ((size_t)n * CO + co4 * 4) * 16);
#pragma unroll
        for (int j = 0; j < 4; j++) {
            float4 x0 = Wv[j], x1 = Wv[4 + j], x2 = Wv[8 + j], x3 = Wv[12 + j];
            w2[j*4+0]      = pack2(x0.x, x1.x);
            w2[j*4+1]      = pack2(x0.y, x1.y);
            w2[j*4+2]      = pack2(x0.z, x1.z);
            w2[j*4+3]      = pack2(x0.w, x1.w);
            w2[16 + j*4+0] = pack2(x2.x, x3.x);
            w2[16 + j*4+1] = pack2(x2.y, x3.y);
            w2[16 + j*4+2] = pack2(x2.z, x3.z);
            w2[16 + j*4+3] = pack2(x2.w, x3.w);
        }
        __syncthreads();

#pragma unroll
        for (int q = 0; q < 8; q++) {
            const int bl = bsub + 4 * q;
            float p[16];
            const float4* pv = (const float4*)(sp + bl * 16);
#pragma unroll
            for (int j = 0; j < 4; j++) {
                float4 x = pv[j];
                p[j*4+0] = x.x; p[j*4+1] = x.y; p[j*4+2] = x.z; p[j*4+3] = x.w;
            }
            u64t a01 = 0ull, a23 = 0ull;
#pragma unroll
            for (int i = 0; i < 16; i++) {
                u64t p2 = pack2(p[i], p[i]);
                a01 = fma2(w2[i],      p2, a01);
                a23 = fma2(w2[16 + i], p2, a23);
            }
            s0acc[q*2+0] = add2(s0acc[q*2+0], a01);
            s0acc[q*2+1] = add2(s0acc[q*2+1], a23);

            float v0, v1, v2, v3;
            unpack2(a01, v0, v1);
            unpack2(a23, v2, v3);
            union { __half2 h[2]; uint2 u; } pk;
            pk.h[0] = __floats2half2_rn(v0, v1);
            pk.h[1] = __floats2half2_rn(v2, v3);
            *(uint2*)(g_votes + ((size_t)(bc * 32 + bl) * NN + n) * ROW + co4 * 4) = pk.u;
        }
    }

    // fused pass-0 accumulation
#pragma unroll
    for (int q = 0; q < 8; q++) {
        const int b = bc * 32 + bsub + 4 * q;
        float v0, v1, v2, v3;
        unpack2(s0acc[q*2+0], v0, v1);
        unpack2(s0acc[q*2+1], v2, v3);
        float* dst = &g_s[0][b * CO + co4 * 4];
        atomicAdd(dst + 0, 0.1f * v0);
        atomicAdd(dst + 1, 0.1f * v1);
        atomicAdd(dst + 2, 0.1f * v2);
        atomicAdd(dst + 3, 0.1f * v3);
    }
}

// ============================================================================
// Kernel B: routing pass over 96 n's. grid (256 b, 12 chunks), 256 threads =
// 16 n-slots x 16 c-lanes (c<10 active). No smem staging: votes LDG'd straight
// to registers; vsum held in registers; no per-iteration syncthreads.
// ============================================================================
template <int PASS>
__global__ __launch_bounds__(256, 3) void route_kernel(
    const float* __restrict__ bias, float* __restrict__ out)
{
    const int b     = blockIdx.x;
    const int chunk = blockIdx.y;
    const int t     = threadIdx.x;
    const int nl    = t >> 4;
    const int cl    = t & 15;

    __shared__ float svsum[160];
    __shared__ float sred[8 * 256];
    __shared__ float ccs[10 * 97];     // [c][n_local] padded stride (PASS 2)

    // recompute vsum from global s partials (warps 0-4 full)
    if (t < 160) {
        float bs = bias[t];
        float v = squash16(g_s[0][b * CO + t] + bs);
        if (PASS == 2)
            v += squash16(g_s[1][b * CO + t] + bs);
        svsum[t] = v;
    }
    __syncthreads();

    // vsum into registers (one-time)
    const bool act = (cl < 10);
    float vs[16];
    {
        const float* src = svsum + (act ? cl : 0) * 16;
#pragma unroll
        for (int j = 0; j < 4; j++) {
            float4 x = *(const float4*)(src + j * 4);
            vs[j*4+0] = x.x; vs[j*4+1] = x.y; vs[j*4+2] = x.z; vs[j*4+3] = x.w;
        }
    }

    float sacc[16];
#pragma unroll
    for (int o = 0; o < 16; o++) sacc[o] = 0.f;

    const __half* base = g_votes + ((size_t)b * NN + (size_t)chunk * RCH) * ROW;

#pragma unroll
    for (int k = 0; k < RCH / 16; k++) {
        const int nloc = k * 16 + nl;
        float vv[16];
        if (act) {
            const uint4* rp = (const uint4*)(base + (size_t)nloc * ROW + cl * 16);
            uint4 q0 = rp[0];
            uint4 q1 = rp[1];
            float2 f;
            f = __half22float2(*(__half2*)&q0.x); vv[0] = f.x; vv[1] = f.y;
            f = __half22float2(*(__half2*)&q0.y); vv[2] = f.x; vv[3] = f.y;
            f = __half22float2(*(__half2*)&q0.z); vv[4] = f.x; vv[5] = f.y;
            f = __half22float2(*(__half2*)&q0.w); vv[6] = f.x; vv[7] = f.y;
            f = __half22float2(*(__half2*)&q1.x); vv[8] = f.x; vv[9] = f.y;
            f = __half22float2(*(__half2*)&q1.y); vv[10] = f.x; vv[11] = f.y;
            f = __half22float2(*(__half2*)&q1.z); vv[12] = f.x; vv[13] = f.y;
            f = __half22float2(*(__half2*)&q1.w); vv[14] = f.x; vv[15] = f.y;
        } else {
#pragma unroll
            for (int o = 0; o < 16; o++) vv[o] = 0.f;
        }

        // logit (no max-subtraction: |logit| is small and bounded)
        float lg = -1e30f;
        if (act) {
            lg = 0.f;
#pragma unroll
            for (int i = 0; i < 16; i++) lg = fmaf(vs[i], vv[i], lg);
        }
        float e = __expf(lg);           // inactive lanes -> 0
        float den = e;
#pragma unroll
        for (int m = 1; m < 16; m <<= 1)
            den += __shfl_xor_sync(0xFFFFFFFFu, den, m, 16);
        float cc = e / den;

#pragma unroll
        for (int o = 0; o < 16; o++) sacc[o] = fmaf(cc, vv[o], sacc[o]);

        if (PASS == 2 && act) ccs[cl * 97 + nloc] = cc;
    }

    // fold the warp's 2 n-slots
#pragma unroll
    for (int o = 0; o < 16; o++)
        sacc[o] += __shfl_xor_sync(0xFFFFFFFFu, sacc[o], 16, 32);

    const int w = t >> 5;
    if ((t & 16) == 0) {
#pragma unroll
        for (int j = 0; j < 4; j++) {
            float4 x = make_float4(sacc[j*4], sacc[j*4+1], sacc[j*4+2], sacc[j*4+3]);
            *(float4*)(sred + w * 256 + cl * 16 + j * 4) = x;
        }
    }
    __syncthreads();

    if (t < 160) {
        float s = 0.f;
#pragma unroll
        for (int w2 = 0; w2 < 8; w2++) s += sred[w2 * 256 + t];
        atomicAdd(&g_s[PASS][b * CO + t], s);
    }

    if (PASS == 2) {
        for (int idx = t; idx < NC * RCH; idx += 256) {
            int c = idx / RCH, nn = idx % RCH;
            out[COUP_OFF + (size_t)b * (NC * NN) + (size_t)c * NN
                + (size_t)chunk * RCH + nn] = ccs[c * 97 + nn];
        }
    }
}

// ============================================================================
// finish2: final outputs from complete s2. grid 256, 160 threads.
// ============================================================================
__global__ __launch_bounds__(160) void finish2_kernel(
    const float* __restrict__ bias, float* __restrict__ out)
{
    const int b = blockIdx.x;
    const int t = threadIdx.x;
    const int c = t >> 4, o = t & 15;

    float v = squash16(g_s[2][b * CO + t] + bias[t]);

    out[POSE_OFF + (size_t)b * CO + t] = v;
    float vsq = v * v;
#pragma unroll
    for (int m = 1; m < 16; m <<= 1)
        vsq += __shfl_xor_sync(0xFFFFFFFFu, vsq, m, 16);
    if (o == 0) out[ACT_OFF + b * NC + c] = sqrtf(vsq + 1e-8f);
}

// ============================================================================
extern "C" void kernel_launch(void* const* d_in, const int* in_sizes, int n_in,
                              void* d_out, int out_size)
{
    const float* P    = (const float*)d_in[0];  // (256,32,6,6,16,1)
    const float* W    = (const float*)d_in[2];  // (32,6,6,10,16,16)
    const float* bias = (const float*)d_in[3];  // (10,1,1,16,1)
    float* out = (float*)d_out;

    init_kernel<<<(3 * NB * CO + 511) / 512, 512>>>();
    votes_kernel<<<dim3(NGRP, 8), 160>>>(P, W);
    route_kernel<1><<<dim3(NB, RSPLIT), 256>>>(bias, out);
    route_kernel<2><<<dim3(NB, RSPLIT), 256>>>(bias, out);
    finish2_kernel<<<NB, 160>>>(bias, out);
}

// round 6
// speedup vs baseline: 1.3923x; 1.3358x over previous
#include <cuda_runtime.h>
#include <cuda_fp16.h>
#include <cstdint>

// ---------------- scratch (static device globals) ---------------------------
__device__ __half g_votes[256u * 1152u * 160u];  // fp16 votes [b][n][co], ~94 MB
__device__ float  g_s[3][256 * 160];             // per-pass s accumulators

// ---------------- constants -------------------------------------------------
#define NB      256
#define NN      1152
#define NC      10
#define CO      160
#define ROW     160            // halves per (b,n) row
#define GN      16             // n's per votes block
#define NGRP    (NN/GN)        // 72
#define RSPLIT  12             // route chunks per batch
#define RCH     (NN/RSPLIT)    // 96 n per chunk
#define POSE_OFF   0
#define ACT_OFF    40960
#define COUP_OFF   43520

// ---------------- f32x2 helpers ---------------------------------------------
typedef unsigned long long u64t;
__device__ __forceinline__ u64t pack2(float lo, float hi) {
    u64t r; asm("mov.b64 %0, {%1, %2};" : "=l"(r) : "f"(lo), "f"(hi)); return r;
}
__device__ __forceinline__ void unpack2(u64t v, float& lo, float& hi) {
    asm("mov.b64 {%0, %1}, %2;" : "=f"(lo), "=f"(hi) : "l"(v));
}
__device__ __forceinline__ u64t fma2(u64t a, u64t b, u64t c) {
    u64t r; asm("fma.rn.f32x2 %0, %1, %2, %3;" : "=l"(r) : "l"(a), "l"(b), "l"(c)); return r;
}
__device__ __forceinline__ u64t add2(u64t a, u64t b) {
    u64t r; asm("add.rn.f32x2 %0, %1, %2;" : "=l"(r) : "l"(a), "l"(b)); return r;
}

// squash over a 16-lane o-group (full-warp participation required)
__device__ __forceinline__ float squash16(float s) {
    float sq = s * s;
#pragma unroll
    for (int m = 1; m < 16; m <<= 1)
        sq += __shfl_xor_sync(0xFFFFFFFFu, sq, m, 16);
    float norm = sqrtf(sq + 1e-8f);
    return sq / (1.0f + sq) * (s / norm);
}

// ============================================================================
// init: zero the s accumulators (re-zeroed every graph replay)
// ============================================================================
__global__ void init_kernel() {
    int i = blockIdx.x * blockDim.x + threadIdx.x;
    if (i < 3 * NB * CO) ((float*)g_s)[i] = 0.f;
}

// ============================================================================
// Kernel A: votes[b,n,co] = sum_i W[n,co,i]*P[b,n,i]  (f32x2, fp16 out)
// fused pass-0: g_s[0][b,co] += 0.1 * sum_n votes.
// grid (72, 8): block = 16 n x 32 b. 320 threads: tco=t%40 owns co-quad
// co4=4*tco; tb=t/40 owns b-quad b4=4*tb (as 2 f32x2 b-pairs).
// W and P staged transposed in smem: wt[i][co], spt[i][b].
// ============================================================================
__global__ __launch_bounds__(320) void votes_kernel(
    const float* __restrict__ P, const float* __restrict__ W)
{
    const int ng  = blockIdx.x;
    const int bc  = blockIdx.y;
    const int t   = threadIdx.x;
    const int tco = t % 40;
    const int tb  = t / 40;
    const int co4 = tco * 4;
    const int b4  = tb * 4;

    __shared__ float wt[16][164];   // [i][co], padded
    __shared__ float spt[16][34];   // [i][b], padded (even pad keeps 8B align)

    u64t s0acc[8];                  // [2*j + pair]: co4+j, b-pair
#pragma unroll
    for (int j = 0; j < 8; j++) s0acc[j] = 0ull;

    for (int g = 0; g < GN; g++) {
        const int n = ng * GN + g;

        __syncthreads();            // previous mainloop reads done

        // stage W[n] transposed: 640 float4, 2 per thread
        {
            const float4* Wn = (const float4*)(W + (size_t)n * (CO * 16));
#pragma unroll
            for (int r = 0; r < 2; r++) {
                int f = t + r * 320;
                float4 x = Wn[f];
                int co = f >> 2, i0 = (f & 3) * 4;
                wt[i0 + 0][co] = x.x; wt[i0 + 1][co] = x.y;
                wt[i0 + 2][co] = x.z; wt[i0 + 3][co] = x.w;
            }
        }
        // stage P[:,n] transposed: 128 float4 by threads 0..127
        if (t < 128) {
            int b = t >> 2, i0 = (t & 3) * 4;
            float4 x = *(const float4*)(P + ((size_t)(bc * 32 + b) * NN + n) * 16 + i0);
            spt[i0 + 0][b] = x.x; spt[i0 + 1][b] = x.y;
            spt[i0 + 2][b] = x.z; spt[i0 + 3][b] = x.w;
        }
        __syncthreads();

        u64t acc[8];
#pragma unroll
        for (int j = 0; j < 8; j++) acc[j] = 0ull;

#pragma unroll
        for (int i = 0; i < 16; i++) {
            float4 w4 = *(const float4*)&wt[i][co4];
            u64t p0 = *(const u64t*)&spt[i][b4];
            u64t p1 = *(const u64t*)&spt[i][b4 + 2];
            u64t ww;
            ww = pack2(w4.x, w4.x); acc[0] = fma2(ww, p0, acc[0]); acc[1] = fma2(ww, p1, acc[1]);
            ww = pack2(w4.y, w4.y); acc[2] = fma2(ww, p0, acc[2]); acc[3] = fma2(ww, p1, acc[3]);
            ww = pack2(w4.z, w4.z); acc[4] = fma2(ww, p0, acc[4]); acc[5] = fma2(ww, p1, acc[5]);
            ww = pack2(w4.w, w4.w); acc[6] = fma2(ww, p0, acc[6]); acc[7] = fma2(ww, p1, acc[7]);
        }

#pragma unroll
        for (int j = 0; j < 8; j++) s0acc[j] = add2(s0acc[j], acc[j]);

        // unpack -> va[bb][j] = vote at (b4+bb, co4+j)
        float va[4][4];
#pragma unroll
        for (int j = 0; j < 4; j++) {
            float lo0, hi0, lo1, hi1;
            unpack2(acc[2*j + 0], lo0, hi0);
            unpack2(acc[2*j + 1], lo1, hi1);
            va[0][j] = lo0; va[1][j] = hi0; va[2][j] = lo1; va[3][j] = hi1;
        }
#pragma unroll
        for (int bb = 0; bb < 4; bb++) {
            union { __half2 h[2]; u64t u; } pk;
            pk.h[0] = __floats2half2_rn(va[bb][0], va[bb][1]);
            pk.h[1] = __floats2half2_rn(va[bb][2], va[bb][3]);
            *(u64t*)(g_votes + ((size_t)(bc * 32 + b4 + bb) * NN + n) * ROW + co4) = pk.u;
        }
    }

    // fused pass-0 atomics (16 per thread)
#pragma unroll
    for (int j = 0; j < 4; j++) {
        float lo0, hi0, lo1, hi1;
        unpack2(s0acc[2*j + 0], lo0, hi0);
        unpack2(s0acc[2*j + 1], lo1, hi1);
        atomicAdd(&g_s[0][(bc * 32 + b4 + 0) * CO + co4 + j], 0.1f * lo0);
        atomicAdd(&g_s[0][(bc * 32 + b4 + 1) * CO + co4 + j], 0.1f * hi0);
        atomicAdd(&g_s[0][(bc * 32 + b4 + 2) * CO + co4 + j], 0.1f * lo1);
        atomicAdd(&g_s[0][(bc * 32 + b4 + 3) * CO + co4 + j], 0.1f * hi1);
    }
}

// ============================================================================
// Kernel B: routing pass over 96 n's. grid (256 b, 12 chunks), 512 threads =
// 16 warps; warp = one n as (16 c-lanes x 2 o-halves). Each thread owns 8 o's:
// per-iter one LDG.128 (warp covers the whole 320B row), logit partial + one
// width-32 shfl to combine halves, width-16 softmax, 8-FMA s accumulation.
// ============================================================================
template <int PASS>
__global__ __launch_bounds__(512) void route_kernel(
    const float* __restrict__ bias, float* __restrict__ out)
{
    const int b     = blockIdx.x;
    const int chunk = blockIdx.y;
    const int t     = threadIdx.x;
    const int w     = t >> 5;
    const int lane  = t & 31;
    const int cl    = lane & 15;
    const int oh    = lane >> 4;

    __shared__ float svsum[160];
    __shared__ float sred[16 * 160];
    __shared__ float ccs[10][97];

    // recompute vsum from global s (pass1: v0; pass2: v0+v1)
    if (t < 160) {
        float bs = bias[t];
        float v = squash16(g_s[0][b * CO + t] + bs);
        if (PASS == 2)
            v += squash16(g_s[1][b * CO + t] + bs);
        svsum[t] = v;
    }
    __syncthreads();

    const bool act = (cl < 10);
    float vs[8];
    {
        const float* src = svsum + (act ? cl : 0) * 16 + oh * 8;
        float4 a = *(const float4*)(src);
        float4 c = *(const float4*)(src + 4);
        vs[0]=a.x; vs[1]=a.y; vs[2]=a.z; vs[3]=a.w;
        vs[4]=c.x; vs[5]=c.y; vs[6]=c.z; vs[7]=c.w;
    }

    float sacc[8];
#pragma unroll
    for (int j = 0; j < 8; j++) sacc[j] = 0.f;

    const __half* base = g_votes + ((size_t)b * NN + (size_t)chunk * RCH) * ROW;

#pragma unroll
    for (int k = 0; k < RCH / 16; k++) {
        const int nloc = k * 16 + w;
        float vv[8];
        if (act) {
            uint4 q = *(const uint4*)(base + (size_t)nloc * ROW + cl * 16 + oh * 8);
            const __half2* hh = (const __half2*)&q;
            float2 f;
            f = __half22float2(hh[0]); vv[0] = f.x; vv[1] = f.y;
            f = __half22float2(hh[1]); vv[2] = f.x; vv[3] = f.y;
            f = __half22float2(hh[2]); vv[4] = f.x; vv[5] = f.y;
            f = __half22float2(hh[3]); vv[6] = f.x; vv[7] = f.y;
        } else {
#pragma unroll
            for (int j = 0; j < 8; j++) vv[j] = 0.f;
        }

        float lg = 0.f;
        if (act) {
#pragma unroll
            for (int j = 0; j < 8; j++) lg = fmaf(vs[j], vv[j], lg);
        }
        lg += __shfl_xor_sync(0xFFFFFFFFu, lg, 16);     // combine o-halves

        float e = act ? __expf(lg) : 0.f;
        float den = e;
#pragma unroll
        for (int m = 1; m < 16; m <<= 1)
            den += __shfl_xor_sync(0xFFFFFFFFu, den, m, 16);
        float cc = e / den;

#pragma unroll
        for (int j = 0; j < 8; j++) sacc[j] = fmaf(cc, vv[j], sacc[j]);

        if (PASS == 2 && act && oh == 0) ccs[cl][nloc] = cc;
    }

    // per-warp partials -> smem -> 160-thread sum -> global atomics
    if (act) {
        float* dst = sred + w * 160 + cl * 16 + oh * 8;
        *(float4*)(dst)     = make_float4(sacc[0], sacc[1], sacc[2], sacc[3]);
        *(float4*)(dst + 4) = make_float4(sacc[4], sacc[5], sacc[6], sacc[7]);
    }
    __syncthreads();

    if (t < 160) {
        float s = 0.f;
#pragma unroll
        for (int w2 = 0; w2 < 16; w2++) s += sred[w2 * 160 + t];
        atomicAdd(&g_s[PASS][b * CO + t], s);
    }

    if (PASS == 2) {
        for (int idx = t; idx < NC * RCH; idx += 512) {
            int c = idx / RCH, nn2 = idx % RCH;
            out[COUP_OFF + (size_t)b * (NC * NN) + (size_t)c * NN
                + (size_t)chunk * RCH + nn2] = ccs[c][nn2];
        }
    }
}

// ============================================================================
// finish2: final outputs from complete s2. grid 256, 160 threads.
// ============================================================================
__global__ __launch_bounds__(160) void finish2_kernel(
    const float* __restrict__ bias, float* __restrict__ out)
{
    const int b = blockIdx.x;
    const int t = threadIdx.x;
    const int c = t >> 4, o = t & 15;

    float v = squash16(g_s[2][b * CO + t] + bias[t]);

    out[POSE_OFF + (size_t)b * CO + t] = v;
    float vsq = v * v;
#pragma unroll
    for (int m = 1; m < 16; m <<= 1)
        vsq += __shfl_xor_sync(0xFFFFFFFFu, vsq, m, 16);
    if (o == 0) out[ACT_OFF + b * NC + c] = sqrtf(vsq + 1e-8f);
}

// ============================================================================
extern "C" void kernel_launch(void* const* d_in, const int* in_sizes, int n_in,
                              void* d_out, int out_size)
{
    const float* P    = (const float*)d_in[0];  // (256,32,6,6,16,1)
    const float* W    = (const float*)d_in[2];  // (32,6,6,10,16,16)
    const float* bias = (const float*)d_in[3];  // (10,1,1,16,1)
    float* out = (float*)d_out;

    init_kernel<<<(3 * NB * CO + 511) / 512, 512>>>();
    votes_kernel<<<dim3(NGRP, 8), 320>>>(P, W);
    route_kernel<1><<<dim3(NB, RSPLIT), 512>>>(bias, out);
    route_kernel<2><<<dim3(NB, RSPLIT), 512>>>(bias, out);
    finish2_kernel<<<NB, 160>>>(bias, out);
}

// round 7
// speedup vs baseline: 2.1349x; 1.5334x over previous
#include <cuda_runtime.h>
#include <cuda_fp16.h>
#include <cstdint>

// ---------------- scratch (static device globals) ---------------------------
__device__ __half g_votes[256u * 1152u * 160u];  // fp16 votes [b][n][co], ~94 MB
__device__ float  g_s[3][256 * 160];             // per-pass s accumulators

// ---------------- constants -------------------------------------------------
#define NB      256
#define NN      1152
#define NC      10
#define CO      160
#define ROW     160            // halves per (b,n) row
#define GN      16             // n's per votes block
#define NGRP    (NN/GN)        // 72
#define RSPLIT  12             // route chunks per batch
#define RCH     (NN/RSPLIT)    // 96 n per chunk
#define POSE_OFF   0
#define ACT_OFF    40960
#define COUP_OFF   43520

// ---------------- f32x2 helpers (votes GEMM) --------------------------------
typedef unsigned long long u64t;
__device__ __forceinline__ u64t pack2(float lo, float hi) {
    u64t r; asm("mov.b64 %0, {%1, %2};" : "=l"(r) : "f"(lo), "f"(hi)); return r;
}
__device__ __forceinline__ void unpack2(u64t v, float& lo, float& hi) {
    asm("mov.b64 {%0, %1}, %2;" : "=f"(lo), "=f"(hi) : "l"(v));
}
__device__ __forceinline__ u64t fma2(u64t a, u64t b, u64t c) {
    u64t r; asm("fma.rn.f32x2 %0, %1, %2, %3;" : "=l"(r) : "l"(a), "l"(b), "l"(c)); return r;
}
__device__ __forceinline__ u64t add2(u64t a, u64t b) {
    u64t r; asm("add.rn.f32x2 %0, %1, %2;" : "=l"(r) : "l"(a), "l"(b)); return r;
}

// squash over a 16-lane o-group (full-warp participation required)
__device__ __forceinline__ float squash16(float s) {
    float sq = s * s;
#pragma unroll
    for (int m = 1; m < 16; m <<= 1)
        sq += __shfl_xor_sync(0xFFFFFFFFu, sq, m, 16);
    float norm = sqrtf(sq + 1e-8f);
    return sq / (1.0f + sq) * (s / norm);
}

// ============================================================================
// init: zero the s accumulators (re-zeroed every graph replay)
// ============================================================================
__global__ void init_kernel() {
    int i = blockIdx.x * blockDim.x + threadIdx.x;
    if (i < 3 * NB * CO) ((float*)g_s)[i] = 0.f;
}

// ============================================================================
// Kernel A (unchanged from R6): votes GEMM, f32x2, fp16 out, fused pass-0.
// ============================================================================
__global__ __launch_bounds__(320) void votes_kernel(
    const float* __restrict__ P, const float* __restrict__ W)
{
    const int ng  = blockIdx.x;
    const int bc  = blockIdx.y;
    const int t   = threadIdx.x;
    const int tco = t % 40;
    const int tb  = t / 40;
    const int co4 = tco * 4;
    const int b4  = tb * 4;

    __shared__ float wt[16][164];   // [i][co], padded
    __shared__ float spt[16][34];   // [i][b], padded

    u64t s0acc[8];
#pragma unroll
    for (int j = 0; j < 8; j++) s0acc[j] = 0ull;

    for (int g = 0; g < GN; g++) {
        const int n = ng * GN + g;

        __syncthreads();

        {
            const float4* Wn = (const float4*)(W + (size_t)n * (CO * 16));
#pragma unroll
            for (int r = 0; r < 2; r++) {
                int f = t + r * 320;
                float4 x = Wn[f];
                int co = f >> 2, i0 = (f & 3) * 4;
                wt[i0 + 0][co] = x.x; wt[i0 + 1][co] = x.y;
                wt[i0 + 2][co] = x.z; wt[i0 + 3][co] = x.w;
            }
        }
        if (t < 128) {
            int b = t >> 2, i0 = (t & 3) * 4;
            float4 x = *(const float4*)(P + ((size_t)(bc * 32 + b) * NN + n) * 16 + i0);
            spt[i0 + 0][b] = x.x; spt[i0 + 1][b] = x.y;
            spt[i0 + 2][b] = x.z; spt[i0 + 3][b] = x.w;
        }
        __syncthreads();

        u64t acc[8];
#pragma unroll
        for (int j = 0; j < 8; j++) acc[j] = 0ull;

#pragma unroll
        for (int i = 0; i < 16; i++) {
            float4 w4 = *(const float4*)&wt[i][co4];
            u64t p0 = *(const u64t*)&spt[i][b4];
            u64t p1 = *(const u64t*)&spt[i][b4 + 2];
            u64t ww;
            ww = pack2(w4.x, w4.x); acc[0] = fma2(ww, p0, acc[0]); acc[1] = fma2(ww, p1, acc[1]);
            ww = pack2(w4.y, w4.y); acc[2] = fma2(ww, p0, acc[2]); acc[3] = fma2(ww, p1, acc[3]);
            ww = pack2(w4.z, w4.z); acc[4] = fma2(ww, p0, acc[4]); acc[5] = fma2(ww, p1, acc[5]);
            ww = pack2(w4.w, w4.w); acc[6] = fma2(ww, p0, acc[6]); acc[7] = fma2(ww, p1, acc[7]);
        }

#pragma unroll
        for (int j = 0; j < 8; j++) s0acc[j] = add2(s0acc[j], acc[j]);

        float va[4][4];
#pragma unroll
        for (int j = 0; j < 4; j++) {
            float lo0, hi0, lo1, hi1;
            unpack2(acc[2*j + 0], lo0, hi0);
            unpack2(acc[2*j + 1], lo1, hi1);
            va[0][j] = lo0; va[1][j] = hi0; va[2][j] = lo1; va[3][j] = hi1;
        }
#pragma unroll
        for (int bb = 0; bb < 4; bb++) {
            union { __half2 h[2]; u64t u; } pk;
            pk.h[0] = __floats2half2_rn(va[bb][0], va[bb][1]);
            pk.h[1] = __floats2half2_rn(va[bb][2], va[bb][3]);
            *(u64t*)(g_votes + ((size_t)(bc * 32 + b4 + bb) * NN + n) * ROW + co4) = pk.u;
        }
    }

#pragma unroll
    for (int j = 0; j < 4; j++) {
        float lo0, hi0, lo1, hi1;
        unpack2(s0acc[2*j + 0], lo0, hi0);
        unpack2(s0acc[2*j + 1], lo1, hi1);
        atomicAdd(&g_s[0][(bc * 32 + b4 + 0) * CO + co4 + j], 0.1f * lo0);
        atomicAdd(&g_s[0][(bc * 32 + b4 + 1) * CO + co4 + j], 0.1f * hi0);
        atomicAdd(&g_s[0][(bc * 32 + b4 + 2) * CO + co4 + j], 0.1f * lo1);
        atomicAdd(&g_s[0][(bc * 32 + b4 + 3) * CO + co4 + j], 0.1f * hi1);
    }
}

// ============================================================================
// Kernel B: routing pass over 96 n's. grid (256 b, 12 chunks), 256 threads =
// 16 n-slots x 16 c-lanes (c<10 active). Half2 datapath: logit via HFMA2
// (2 accumulators, fp32 combine), softmax with fast division, s accumulated
// in half2 (only 6 adds) and converted to fp32 at the epilogue.
// ============================================================================
template <int PASS>
__global__ __launch_bounds__(256) void route_kernel(
    const float* __restrict__ bias, float* __restrict__ out)
{
    const int b     = blockIdx.x;
    const int chunk = blockIdx.y;
    const int t     = threadIdx.x;
    const int nl    = t >> 4;
    const int cl    = t & 15;

    __shared__ float svsum[160];
    __shared__ float sred[8 * 160];
    __shared__ float ccs[10][97];

    // recompute vsum from global s (pass1: v0; pass2: v0+v1)
    if (t < 160) {
        float bs = bias[t];
        float v = squash16(g_s[0][b * CO + t] + bs);
        if (PASS == 2)
            v += squash16(g_s[1][b * CO + t] + bs);
        svsum[t] = v;
    }
    __syncthreads();

    const bool act = (cl < 10);

    // vsum for this c-lane, packed to half2 (one-time)
    __half2 vsh[8];
    {
        const float* src = svsum + (act ? cl : 0) * 16;
#pragma unroll
        for (int j = 0; j < 8; j++)
            vsh[j] = __floats2half2_rn(src[2*j], src[2*j + 1]);
    }

    __half2 sacc[8];
#pragma unroll
    for (int j = 0; j < 8; j++) sacc[j] = __float2half2_rn(0.f);

    const __half* base = g_votes + ((size_t)b * NN + (size_t)chunk * RCH) * ROW;

#pragma unroll
    for (int k = 0; k < RCH / 16; k++) {
        const int nloc = k * 16 + nl;
        __half2 vv[8];
        float lg = 0.f;
        if (act) {
            const uint4* rp = (const uint4*)(base + (size_t)nloc * ROW + cl * 16);
            uint4 q0 = rp[0];
            uint4 q1 = rp[1];
            vv[0] = *(__half2*)&q0.x; vv[1] = *(__half2*)&q0.y;
            vv[2] = *(__half2*)&q0.z; vv[3] = *(__half2*)&q0.w;
            vv[4] = *(__half2*)&q1.x; vv[5] = *(__half2*)&q1.y;
            vv[6] = *(__half2*)&q1.z; vv[7] = *(__half2*)&q1.w;

            // logit dot: two independent half2 accumulators, fp32 combine
            __half2 la = __hmul2(vv[0], vsh[0]);
            __half2 lb = __hmul2(vv[1], vsh[1]);
            la = __hfma2(vv[2], vsh[2], la);
            lb = __hfma2(vv[3], vsh[3], lb);
            la = __hfma2(vv[4], vsh[4], la);
            lb = __hfma2(vv[5], vsh[5], lb);
            la = __hfma2(vv[6], vsh[6], la);
            lb = __hfma2(vv[7], vsh[7], lb);
            float2 fa = __half22float2(la);
            float2 fb = __half22float2(lb);
            lg = (fa.x + fa.y) + (fb.x + fb.y);
        }

        float e = act ? __expf(lg) : 0.f;
        float den = e;
#pragma unroll
        for (int m = 1; m < 16; m <<= 1)
            den += __shfl_xor_sync(0xFFFFFFFFu, den, m, 16);
        float cc = __fdividef(e, den);

        if (act) {
            __half2 cch = __float2half2_rn(cc);
#pragma unroll
            for (int j = 0; j < 8; j++) sacc[j] = __hfma2(cch, vv[j], sacc[j]);
            if (PASS == 2) ccs[cl][nloc] = cc;
        }
    }

    // ---- convert sacc to fp32, fold warp's 2 n-slots, reduce, atomics ----
    float sf[16];
#pragma unroll
    for (int j = 0; j < 8; j++) {
        float2 f = __half22float2(sacc[j]);
        sf[2*j] = f.x; sf[2*j + 1] = f.y;
    }
#pragma unroll
    for (int o = 0; o < 16; o++)
        sf[o] += __shfl_xor_sync(0xFFFFFFFFu, sf[o], 16, 32);

    const int w = t >> 5;
    if ((t & 16) == 0) {
        float* dst = sred + w * 160 + cl * 16;   // cl<10 only meaningful
        if (act) {
#pragma unroll
            for (int j = 0; j < 4; j++)
                *(float4*)(dst + j * 4) =
                    make_float4(sf[j*4], sf[j*4+1], sf[j*4+2], sf[j*4+3]);
        }
    }
    __syncthreads();

    if (t < 160) {
        float s = 0.f;
#pragma unroll
        for (int w2 = 0; w2 < 8; w2++) s += sred[w2 * 160 + t];
        atomicAdd(&g_s[PASS][b * CO + t], s);
    }

    if (PASS == 2) {
        for (int idx = t; idx < NC * RCH; idx += 256) {
            int c = idx / RCH, nn2 = idx % RCH;
            out[COUP_OFF + (size_t)b * (NC * NN) + (size_t)c * NN
                + (size_t)chunk * RCH + nn2] = ccs[c][nn2];
        }
    }
}

// ============================================================================
// finish2: final outputs from complete s2. grid 256, 160 threads.
// ============================================================================
__global__ __launch_bounds__(160) void finish2_kernel(
    const float* __restrict__ bias, float* __restrict__ out)
{
    const int b = blockIdx.x;
    const int t = threadIdx.x;
    const int c = t >> 4, o = t & 15;

    float v = squash16(g_s[2][b * CO + t] + bias[t]);

    out[POSE_OFF + (size_t)b * CO + t] = v;
    float vsq = v * v;
#pragma unroll
    for (int m = 1; m < 16; m <<= 1)
        vsq += __shfl_xor_sync(0xFFFFFFFFu, vsq, m, 16);
    if (o == 0) out[ACT_OFF + b * NC + c] = sqrtf(vsq + 1e-8f);
}

// ============================================================================
extern "C" void kernel_launch(void* const* d_in, const int* in_sizes, int n_in,
                              void* d_out, int out_size)
{
    const float* P    = (const float*)d_in[0];  // (256,32,6,6,16,1)
    const float* W    = (const float*)d_in[2];  // (32,6,6,10,16,16)
    const float* bias = (const float*)d_in[3];  // (10,1,1,16,1)
    float* out = (float*)d_out;

    init_kernel<<<(3 * NB * CO + 511) / 512, 512>>>();
    votes_kernel<<<dim3(NGRP, 8), 320>>>(P, W);
    route_kernel<1><<<dim3(NB, RSPLIT), 256>>>(bias, out);
    route_kernel<2><<<dim3(NB, RSPLIT), 256>>>(bias, out);
    finish2_kernel<<<NB, 160>>>(bias, out);
}

// round 8
// speedup vs baseline: 2.5159x; 1.1785x over previous
#include <cuda_runtime.h>
#include <cuda_fp16.h>
#include <cstdint>

// ---------------- scratch (static device globals) ---------------------------
__device__ __half g_votes[256u * 1152u * 160u];  // fp16 votes [b][n][co], ~94 MB
__device__ float  g_s[3][256 * 160];             // per-pass s accumulators

// ---------------- constants -------------------------------------------------
#define NB      256
#define NN      1152
#define NC      10
#define CO      160
#define ROW     160            // halves per (b,n) row
#define GN      16             // n's per votes block
#define NGRP    (NN/GN)        // 72
#define RSPLIT  12             // route chunks per batch
#define RCH     (NN/RSPLIT)    // 96 n per chunk
#define POSE_OFF   0
#define ACT_OFF    40960
#define COUP_OFF   43520

// ---------------- f32x2 helpers (votes GEMM) --------------------------------
typedef unsigned long long u64t;
__device__ __forceinline__ u64t pack2(float lo, float hi) {
    u64t r; asm("mov.b64 %0, {%1, %2};" : "=l"(r) : "f"(lo), "f"(hi)); return r;
}
__device__ __forceinline__ void unpack2(u64t v, float& lo, float& hi) {
    asm("mov.b64 {%0, %1}, %2;" : "=f"(lo), "=f"(hi) : "l"(v));
}
__device__ __forceinline__ u64t fma2(u64t a, u64t b, u64t c) {
    u64t r; asm("fma.rn.f32x2 %0, %1, %2, %3;" : "=l"(r) : "l"(a), "l"(b), "l"(c)); return r;
}

__device__ __forceinline__ void stcs_f32(float* p, float v) {
    asm volatile("st.global.cs.f32 [%0], %1;" :: "l"(p), "f"(v));
}

// squash over a 16-lane o-group (full-warp participation required)
__device__ __forceinline__ float squash16(float s) {
    float sq = s * s;
#pragma unroll
    for (int m = 1; m < 16; m <<= 1)
        sq += __shfl_xor_sync(0xFFFFFFFFu, sq, m, 16);
    float norm = sqrtf(sq + 1e-8f);
    return sq / (1.0f + sq) * (s / norm);
}

// ============================================================================
// init: zero the s accumulators (re-zeroed every graph replay)
// ============================================================================
__global__ void init_kernel() {
    int i = blockIdx.x * blockDim.x + threadIdx.x;
    if (i < 3 * NB * CO) ((float*)g_s)[i] = 0.f;
}

// ============================================================================
// Kernel A: votes[b,n,co] = sum_i W[n,co,i]*P[b,n,i]  (f32x2, fp16 out)
// fused pass-0: g_s[0][b,co] += 0.1 * sum_n votes.
// grid (4 bc, 72 ng): block = 16 n x 64 b  [bc FASTEST so scheduling tail is
// high-n for all b -> chains into route1 reversed]. 320 threads:
//   tco=t%40 owns co-quad co4; tb=t/40 owns 8 b's (4 f32x2 b-pairs).
// Per i: 1 LDS.128 (w) + 4 LDS.64 (p pairs, broadcast) + 4 packs + 16 FFMA2.
// ============================================================================
__global__ __launch_bounds__(320, 2) void votes_kernel(
    const float* __restrict__ P, const float* __restrict__ W)
{
    const int bc  = blockIdx.x;     // 0..3 -> 64 b
    const int ng  = blockIdx.y;     // 0..71 -> 16 n
    const int t   = threadIdx.x;
    const int tco = t % 40;
    const int tb  = t / 40;
    const int co4 = tco * 4;
    const int b8  = tb * 8;

    __shared__ float wt[16][164];   // [i][co], padded
    __shared__ float spt[16][66];   // [i][b], padded

    u64t s0acc[16];                 // [j*4+k]: co4+j, b-pair k
#pragma unroll
    for (int j = 0; j < 16; j++) s0acc[j] = 0ull;

    for (int g = 0; g < GN; g++) {
        const int n = ng * GN + g;

        __syncthreads();            // previous mainloop reads done

        // stage W[n] transposed: 640 float4, 2 per thread
        {
            const float4* Wn = (const float4*)(W + (size_t)n * (CO * 16));
#pragma unroll
            for (int r = 0; r < 2; r++) {
                int f = t + r * 320;
                float4 x = Wn[f];
                int co = f >> 2, i0 = (f & 3) * 4;
                wt[i0 + 0][co] = x.x; wt[i0 + 1][co] = x.y;
                wt[i0 + 2][co] = x.z; wt[i0 + 3][co] = x.w;
            }
        }
        // stage P[:,n] transposed: 256 float4 by threads 0..255
        if (t < 256) {
            int b = t >> 2, i0 = (t & 3) * 4;
            float4 x = *(const float4*)(P + ((size_t)(bc * 64 + b) * NN + n) * 16 + i0);
            spt[i0 + 0][b] = x.x; spt[i0 + 1][b] = x.y;
            spt[i0 + 2][b] = x.z; spt[i0 + 3][b] = x.w;
        }
        __syncthreads();

        u64t acc[16];
#pragma unroll
        for (int j = 0; j < 16; j++) acc[j] = 0ull;

#pragma unroll
        for (int i = 0; i < 16; i++) {
            float4 w4 = *(const float4*)&wt[i][co4];
            u64t p0 = *(const u64t*)&spt[i][b8 + 0];
            u64t p1 = *(const u64t*)&spt[i][b8 + 2];
            u64t p2 = *(const u64t*)&spt[i][b8 + 4];
            u64t p3 = *(const u64t*)&spt[i][b8 + 6];
            u64t ww;
            ww = pack2(w4.x, w4.x);
            acc[0]  = fma2(ww, p0, acc[0]);  acc[1]  = fma2(ww, p1, acc[1]);
            acc[2]  = fma2(ww, p2, acc[2]);  acc[3]  = fma2(ww, p3, acc[3]);
            ww = pack2(w4.y, w4.y);
            acc[4]  = fma2(ww, p0, acc[4]);  acc[5]  = fma2(ww, p1, acc[5]);
            acc[6]  = fma2(ww, p2, acc[6]);  acc[7]  = fma2(ww, p3, acc[7]);
            ww = pack2(w4.z, w4.z);
            acc[8]  = fma2(ww, p0, acc[8]);  acc[9]  = fma2(ww, p1, acc[9]);
            acc[10] = fma2(ww, p2, acc[10]); acc[11] = fma2(ww, p3, acc[11]);
            ww = pack2(w4.w, w4.w);
            acc[12] = fma2(ww, p0, acc[12]); acc[13] = fma2(ww, p1, acc[13]);
            acc[14] = fma2(ww, p2, acc[14]); acc[15] = fma2(ww, p3, acc[15]);
        }

        // accumulate s0 and store votes (8 b x 4 co per thread)
#pragma unroll
        for (int k = 0; k < 4; k++) {
            float lo[4], hi[4];
#pragma unroll
            for (int j = 0; j < 4; j++) {
                u64t a = acc[j * 4 + k];
                s0acc[j * 4 + k] = fma2(pack2(1.f, 1.f), a, s0acc[j * 4 + k]);
                unpack2(a, lo[j], hi[j]);
            }
            union { __half2 h[2]; u64t u; } pk;
            pk.h[0] = __floats2half2_rn(lo[0], lo[1]);
            pk.h[1] = __floats2half2_rn(lo[2], lo[3]);
            *(u64t*)(g_votes + ((size_t)(bc * 64 + b8 + 2*k) * NN + n) * ROW + co4) = pk.u;
            pk.h[0] = __floats2half2_rn(hi[0], hi[1]);
            pk.h[1] = __floats2half2_rn(hi[2], hi[3]);
            *(u64t*)(g_votes + ((size_t)(bc * 64 + b8 + 2*k + 1) * NN + n) * ROW + co4) = pk.u;
        }
    }

    // fused pass-0 atomics (32 per thread)
#pragma unroll
    for (int k = 0; k < 4; k++) {
#pragma unroll
        for (int j = 0; j < 4; j++) {
            float lo, hi;
            unpack2(s0acc[j * 4 + k], lo, hi);
            atomicAdd(&g_s[0][(bc * 64 + b8 + 2*k)     * CO + co4 + j], 0.1f * lo);
            atomicAdd(&g_s[0][(bc * 64 + b8 + 2*k + 1) * CO + co4 + j], 0.1f * hi);
        }
    }
}

// ============================================================================
// Kernel B: routing pass over 96 n's. grid (256 b, 12 chunks), 256 threads =
// 16 n-slots x 16 c-lanes (c<10 active). Half2 datapath.
// REV=1 reverses chunk order so this pass starts where the producer ended
// (L2 chaining): votes tail = high n -> route1 REV=1; route1 tail = low
// chunks -> route2 REV=0.
// ============================================================================
template <int PASS, int REV>
__global__ __launch_bounds__(256) void route_kernel(
    const float* __restrict__ bias, float* __restrict__ out)
{
    const int b     = blockIdx.x;
    const int chunk = REV ? (RSPLIT - 1 - (int)blockIdx.y) : (int)blockIdx.y;
    const int t     = threadIdx.x;
    const int nl    = t >> 4;
    const int cl    = t & 15;

    __shared__ float svsum[160];
    __shared__ float sred[8 * 160];
    __shared__ float ccs[10][97];

    // recompute vsum from global s (pass1: v0; pass2: v0+v1)
    if (t < 160) {
        float bs = bias[t];
        float v = squash16(g_s[0][b * CO + t] + bs);
        if (PASS == 2)
            v += squash16(g_s[1][b * CO + t] + bs);
        svsum[t] = v;
    }
    __syncthreads();

    const bool act = (cl < 10);

    __half2 vsh[8];
    {
        const float* src = svsum + (act ? cl : 0) * 16;
#pragma unroll
        for (int j = 0; j < 8; j++)
            vsh[j] = __floats2half2_rn(src[2*j], src[2*j + 1]);
    }

    __half2 sacc[8];
#pragma unroll
    for (int j = 0; j < 8; j++) sacc[j] = __float2half2_rn(0.f);

    const __half* base = g_votes + ((size_t)b * NN + (size_t)chunk * RCH) * ROW;

#pragma unroll
    for (int k = 0; k < RCH / 16; k++) {
        const int nloc = k * 16 + nl;
        __half2 vv[8];
        float lg = 0.f;
        if (act) {
            const uint4* rp = (const uint4*)(base + (size_t)nloc * ROW + cl * 16);
            uint4 q0 = rp[0];
            uint4 q1 = rp[1];
            vv[0] = *(__half2*)&q0.x; vv[1] = *(__half2*)&q0.y;
            vv[2] = *(__half2*)&q0.z; vv[3] = *(__half2*)&q0.w;
            vv[4] = *(__half2*)&q1.x; vv[5] = *(__half2*)&q1.y;
            vv[6] = *(__half2*)&q1.z; vv[7] = *(__half2*)&q1.w;

            __half2 la = __hmul2(vv[0], vsh[0]);
            __half2 lb = __hmul2(vv[1], vsh[1]);
            la = __hfma2(vv[2], vsh[2], la);
            lb = __hfma2(vv[3], vsh[3], lb);
            la = __hfma2(vv[4], vsh[4], la);
            lb = __hfma2(vv[5], vsh[5], lb);
            la = __hfma2(vv[6], vsh[6], la);
            lb = __hfma2(vv[7], vsh[7], lb);
            float2 fa = __half22float2(la);
            float2 fb = __half22float2(lb);
            lg = (fa.x + fa.y) + (fb.x + fb.y);
        }

        float e = act ? __expf(lg) : 0.f;
        float den = e;
#pragma unroll
        for (int m = 1; m < 16; m <<= 1)
            den += __shfl_xor_sync(0xFFFFFFFFu, den, m, 16);
        float cc = __fdividef(e, den);

        if (act) {
            __half2 cch = __float2half2_rn(cc);
#pragma unroll
            for (int j = 0; j < 8; j++) sacc[j] = __hfma2(cch, vv[j], sacc[j]);
            if (PASS == 2) ccs[cl][nloc] = cc;
        }
    }

    // ---- convert sacc to fp32, fold warp's 2 n-slots, reduce, atomics ----
    float sf[16];
#pragma unroll
    for (int j = 0; j < 8; j++) {
        float2 f = __half22float2(sacc[j]);
        sf[2*j] = f.x; sf[2*j + 1] = f.y;
    }
#pragma unroll
    for (int o = 0; o < 16; o++)
        sf[o] += __shfl_xor_sync(0xFFFFFFFFu, sf[o], 16, 32);

    const int w = t >> 5;
    if ((t & 16) == 0 && act) {
        float* dst = sred + w * 160 + cl * 16;
#pragma unroll
        for (int j = 0; j < 4; j++)
            *(float4*)(dst + j * 4) =
                make_float4(sf[j*4], sf[j*4+1], sf[j*4+2], sf[j*4+3]);
    }
    __syncthreads();

    if (t < 160) {
        float s = 0.f;
#pragma unroll
        for (int w2 = 0; w2 < 8; w2++) s += sred[w2 * 160 + t];
        atomicAdd(&g_s[PASS][b * CO + t], s);
    }

    if (PASS == 2) {
        for (int idx = t; idx < NC * RCH; idx += 256) {
            int c = idx / RCH, nn2 = idx % RCH;
            stcs_f32(out + COUP_OFF + (size_t)b * (NC * NN) + (size_t)c * NN
                     + (size_t)chunk * RCH + nn2, ccs[c][nn2]);
        }
    }
}

// ============================================================================
// finish2: final outputs from complete s2. grid 256, 160 threads.
// ============================================================================
__global__ __launch_bounds__(160) void finish2_kernel(
    const float* __restrict__ bias, float* __restrict__ out)
{
    const int b = blockIdx.x;
    const int t = threadIdx.x;
    const int c = t >> 4, o = t & 15;

    float v = squash16(g_s[2][b * CO + t] + bias[t]);

    stcs_f32(out + POSE_OFF + (size_t)b * CO + t, v);
    float vsq = v * v;
#pragma unroll
    for (int m = 1; m < 16; m <<= 1)
        vsq += __shfl_xor_sync(0xFFFFFFFFu, vsq, m, 16);
    if (o == 0) stcs_f32(out + ACT_OFF + b * NC + c, sqrtf(vsq + 1e-8f));
}

// ============================================================================
extern "C" void kernel_launch(void* const* d_in, const int* in_sizes, int n_in,
                              void* d_out, int out_size)
{
    const float* P    = (const float*)d_in[0];  // (256,32,6,6,16,1)
    const float* W    = (const float*)d_in[2];  // (32,6,6,10,16,16)
    const float* bias = (const float*)d_in[3];  // (10,1,1,16,1)
    float* out = (float*)d_out;

    init_kernel<<<(3 * NB * CO + 511) / 512, 512>>>();
    votes_kernel<<<dim3(4, NGRP), 320>>>(P, W);
    route_kernel<1, 1><<<dim3(NB, RSPLIT), 256>>>(bias, out);
    route_kernel<2, 0><<<dim3(NB, RSPLIT), 256>>>(bias, out);
    finish2_kernel<<<NB, 160>>>(bias, out);
}